// round 13
// baseline (speedup 1.0000x reference)
#include <cuda_runtime.h>
#include <cuda_bf16.h>
#include <cuda_fp16.h>
#include <cstdint>
#include <cstddef>

#define B_   64
#define S_   256
#define D_   512
#define H_   1024
#define G4_  4096
#define NCTA 128
#define RSTR 66
#define EPOCH 255

// ---------------- scratch (device globals) ----------------
__device__ __align__(128) float g_gx[67108864];            // [S][4H][B] (layer0 only)
__device__ __align__(128) float g_h2[16777216];            // [S][H][B]
__device__ __align__(128) unsigned char g_WF[33554432];    // A fragments: slot0=Whh0, slot1=Whh1, slot2=Wih1
__device__ __align__(128) unsigned char g_WI[8388608];     // layer0 input-GEMM A fragments
__device__ __align__(128) unsigned char g_xf[16777216];    // layer0 input-GEMM B fragments
__device__ __align__(128) unsigned char g_h1frag[262144];  // [buf][...] h1 fragments (fp16)
__device__ __align__(128) unsigned char g_h2frag[262144];  // [buf][...] h2 fragments (fp16)
__device__ int g_flags[256];    // flag1[0..127], epoch1 at [EPOCH]
__device__ int g_flags2[256];   // flag2[0..127], epoch2 at [EPOCH]

// ---------------- helpers ----------------
__device__ __forceinline__ float sigf(float x)   { return 1.f / (1.f + __expf(-x)); }
__device__ __forceinline__ float tanhf_(float x) { return 2.f / (1.f + __expf(-2.f * x)) - 1.f; }
__device__ __forceinline__ float actf(float x)   { return x > 0.f ? 1.f / (1.f + __expf(-x)) : 0.5f; }

__device__ __forceinline__ unsigned short f16of(float v) {
    __half h = __float2half(v);
    return *(unsigned short*)&h;
}

__device__ __forceinline__ void mma16816(float* d, const unsigned* a, unsigned b0, unsigned b1) {
    asm volatile("mma.sync.aligned.m16n8k16.row.col.f32.f16.f16.f32 "
                 "{%0,%1,%2,%3}, {%4,%5,%6,%7}, {%8,%9}, {%0,%1,%2,%3};"
                 : "+f"(d[0]), "+f"(d[1]), "+f"(d[2]), "+f"(d[3])
                 : "r"(a[0]), "r"(a[1]), "r"(a[2]), "r"(a[3]), "r"(b0), "r"(b1));
}

// B-fragment byte offset within one s (validated layout)
__device__ __forceinline__ size_t xf_byte(int k, int n) {
    int ktile = k >> 4, kk = k & 15;
    int nt = n >> 3;
    int flane = (n & 7) * 4 + ((kk & 7) >> 1);
    return (((size_t)(ktile * 4 + (nt >> 1)) * 32 + flane) * 16)
           + (size_t)(nt & 1) * 8 + (kk >> 3) * 4 + (kk & 1) * 2;
}

// ---------------- prep: W_ih0 -> A fragments (fp16) ----------------
template<int KT, int KDIM>
__global__ void __launch_bounds__(256)
prep_wi_kernel(const float* __restrict__ W)
{
    unsigned idx  = blockIdx.x * 256 + threadIdx.x;
    unsigned lane = idx & 31;
    unsigned kt   = (idx >> 5) & (KT - 1);
    unsigned w    = (idx >> 5) / KT & 7;
    unsigned gt   = (idx >> 5) / KT >> 3;

    unsigned hi[4];
#pragma unroll
    for (int p = 0; p < 4; ++p) {
        unsigned r = (lane >> 2) + (p & 1) * 8;
        unsigned c = (lane & 3) * 2 + (p >> 1) * 8;
        unsigned row = gt * 128 + w * 16 + r;
        unsigned k = kt * 16 + c;
        float2 v = *(const float2*)(W + (size_t)row * KDIM + k);
        hi[p] = (unsigned)f16of(v.x) | ((unsigned)f16of(v.y) << 16);
    }
    size_t fu = ((size_t)(gt * 8 + w) * KT + kt) * 32 + lane;
    ((uint4*)g_WI)[fu] = make_uint4(hi[0], hi[1], hi[2], hi[3]);
}

// ---------------- conv: x [B][S][D] -> B fragments (K=512) ----------------
__global__ void __launch_bounds__(256)
conv_x0_kernel(const float* __restrict__ x)
{
    unsigned idx = blockIdx.x * 256 + threadIdx.x;
    unsigned k4  = idx & 127;
    unsigned n   = (idx >> 7) & 63;
    unsigned s   = idx >> 13;
    float4 v = *(const float4*)(x + ((size_t)n * S_ + s) * D_ + k4 * 4);
    unsigned char* bs = g_xf + (size_t)s * 65536;
    int k = k4 * 4;
    unsigned u0 = (unsigned)f16of(v.x) | ((unsigned)f16of(v.y) << 16);
    unsigned u1 = (unsigned)f16of(v.z) | ((unsigned)f16of(v.w) << 16);
    *(unsigned*)(bs + xf_byte(k, n))     = u0;
    *(unsigned*)(bs + xf_byte(k + 2, n)) = u1;
}

// ---------------- tensor-core layer0 input GEMM with smem B staging ----------------
template<int KT>
__global__ void __launch_bounds__(256)
gemm_mma_kernel(const uint4* __restrict__ WI, const uint4* __restrict__ XF,
                const float* __restrict__ bA, const float* __restrict__ bB,
                float* __restrict__ gx)
{
    extern __shared__ uint4 Bs[];   // [2][2048]
    const int tid = threadIdx.x, w = tid >> 5, lane = tid & 31;
    const int gt = blockIdx.x;
    const int s0 = blockIdx.y * 2;
    const int NCHUNK = KT / 8;

    float acc[2][8][4];
#pragma unroll
    for (int si = 0; si < 2; ++si)
#pragma unroll
        for (int nt = 0; nt < 8; ++nt)
#pragma unroll
            for (int q = 0; q < 4; ++q) acc[si][nt][q] = 0.f;

    const uint4* ap = WI + ((size_t)(gt * 8 + w) * KT) * 32 + lane;

    auto issue_chunk = [&](int c, int buf) {
        const uint4* base0 = XF + (size_t)s0 * (KT * 128) + c * 1024;
        const uint4* base1 = base0 + KT * 128;
#pragma unroll
        for (int i = 0; i < 8; ++i) {
            int e = tid + i * 256;
            const uint4* src = (e < 1024) ? (base0 + e) : (base1 + (e - 1024));
            unsigned dst = (unsigned)__cvta_generic_to_shared(Bs + buf * 2048 + e);
            asm volatile("cp.async.cg.shared.global [%0], [%1], 16;" :: "r"(dst), "l"(src));
        }
        asm volatile("cp.async.commit_group;" ::: "memory");
    };

    issue_chunk(0, 0);
    asm volatile("cp.async.wait_group 0;" ::: "memory");
    __syncthreads();

    int buf = 0;
    for (int c = 0; c < NCHUNK; ++c) {
        if (c < NCHUNK - 1) issue_chunk(c + 1, buf ^ 1);

        uint4 As[8];
#pragma unroll
        for (int ktl = 0; ktl < 8; ++ktl) As[ktl] = ap[(size_t)(c * 8 + ktl) * 32];
#pragma unroll
        for (int ktl = 0; ktl < 8; ++ktl) {
            unsigned Ah[4] = {As[ktl].x, As[ktl].y, As[ktl].z, As[ktl].w};
            const uint4* q0 = Bs + buf * 2048 + ktl * 128 + lane;
            const uint4* q1 = q0 + 1024;
#pragma unroll
            for (int ntp = 0; ntp < 4; ++ntp) {
                uint4 B0 = q0[ntp * 32];
                mma16816(acc[0][ntp * 2],     Ah, B0.x, B0.y);
                mma16816(acc[0][ntp * 2 + 1], Ah, B0.z, B0.w);
                uint4 B1 = q1[ntp * 32];
                mma16816(acc[1][ntp * 2],     Ah, B1.x, B1.y);
                mma16816(acc[1][ntp * 2 + 1], Ah, B1.z, B1.w);
            }
        }
        if (c < NCHUNK - 1) {
            asm volatile("cp.async.wait_group 0;" ::: "memory");
            __syncthreads();
            buf ^= 1;
        }
    }

    const int r0 = lane >> 2, c0 = (lane & 3) * 2;
    const int gl = gt * 128 + w * 16 + r0;
    const float biasL = bA[gl] + bB[gl];
    const float biasH = bA[gl + 8] + bB[gl + 8];
#pragma unroll
    for (int si = 0; si < 2; ++si) {
        float* gxs = gx + (size_t)(s0 + si) * G4_ * B_;
#pragma unroll
        for (int nt = 0; nt < 8; ++nt) {
            int c = nt * 8 + c0;
            *(float2*)(gxs + (size_t)gl * B_ + c) =
                make_float2(acc[si][nt][0] + biasL, acc[si][nt][1] + biasL);
            *(float2*)(gxs + (size_t)(gl + 8) * B_ + c) =
                make_float2(acc[si][nt][2] + biasH, acc[si][nt][3] + biasH);
        }
    }
}

// ---------------- weight prep: {Whh0, Whh1, Wih1} -> gate-interleaved A fragments ----------------
__global__ void __launch_bounds__(256)
prep_w_kernel(const float* __restrict__ Whh0, const float* __restrict__ Whh1,
              const float* __restrict__ Wih1)
{
    unsigned idx  = blockIdx.x * 256 + threadIdx.x;
    unsigned lane = idx & 31;
    unsigned kt   = (idx >> 5) & 7;
    unsigned mt   = (idx >> 8) & 1;
    unsigned w    = (idx >> 9) & 7;
    unsigned cta  = (idx >> 12) & 127;
    unsigned l    = idx >> 19;
    const float* W = (l == 0) ? Whh0 : (l == 1 ? Whh1 : Wih1);

    unsigned hi[4];
#pragma unroll
    for (int p = 0; p < 4; ++p) {
        unsigned r = (lane >> 2) + (p & 1) * 8;
        unsigned c = (lane & 3) * 2 + (p >> 1) * 8;
        unsigned rloc = mt * 16 + r;
        unsigned gr = cta * 32 + rloc;
        unsigned j = gr >> 2, gate = gr & 3;
        unsigned k = w * 128 + kt * 16 + c;
        float2 v = *(const float2*)(W + ((size_t)(gate * H_ + j)) * H_ + k);
        hi[p] = (unsigned)f16of(v.x) | ((unsigned)f16of(v.y) << 16);
    }
    size_t fr = ((((size_t)(l * 128 + cta) * 8 + w) * 2 + mt) * 8 + kt) * 32 + lane;
    ((uint4*)g_WF)[fr] = make_uint4(hi[0], hi[1], hi[2], hi[3]);
}

__global__ void reset_flags_kernel() {
    g_flags[threadIdx.x] = 0;
    g_flags2[threadIdx.x] = 0;
}

// ---------------- fused 2-layer wavefront recurrence, dual-epoch pipelined ----------------
// Superstep s: (R) Whh1@h2[s-2] behind epoch2 (published mid-superstep s-1),
//              then wait epoch1, merged Whh0/Wih1@h1[s-1], epilogue B (h2[s-1], early flag2),
//              epilogue A (h1[s]), flag1.
__global__ void __launch_bounds__(256, 1)
fused_recur_kernel(const float* __restrict__ gx,
                   const float* __restrict__ bih1, const float* __restrict__ bhh1,
                   float* __restrict__ hseq2)
{
    extern __shared__ float Rbuf[];     // [2][8][32][RSTR]
    float* RbufA = Rbuf;
    float* RbufB = Rbuf + 8 * 32 * RSTR;

    const int tid  = threadIdx.x;
    const int w    = tid >> 5;
    const int lane = tid & 31;
    const int cta  = blockIdx.x;

    // resident A: layer0 recurrence (slot 0)
    unsigned A0[2][8][4];
    {
        const uint4* wf = (const uint4*)g_WF + (((size_t)cta * 8 + w) * 16) * 32 + lane;
#pragma unroll
        for (int mt = 0; mt < 2; ++mt)
#pragma unroll
            for (int kt = 0; kt < 8; ++kt) {
                uint4 h = wf[(size_t)(mt * 8 + kt) * 32];
                A0[mt][kt][0] = h.x; A0[mt][kt][1] = h.y; A0[mt][kt][2] = h.z; A0[mt][kt][3] = h.w;
            }
    }
    const uint4* wfR = (const uint4*)g_WF + (((size_t)(128 + cta) * 8 + w) * 16) * 32 + lane;
    const uint4* wfI = (const uint4*)g_WF + (((size_t)(256 + cta) * 8 + w) * 16) * 32 + lane;

    const int n   = tid & 63;
    const int jl0 = tid >> 6;
    float c0[2] = {0.f, 0.f}, c1[2] = {0.f, 0.f};

    float b1v[2][4];
#pragma unroll
    for (int ci = 0; ci < 2; ++ci) {
        int j = cta * 8 + jl0 + ci * 4;
#pragma unroll
        for (int g = 0; g < 4; ++g) b1v[ci][g] = bih1[g * H_ + j] + bhh1[g * H_ + j];
    }

    volatile int* vf1 = (volatile int*)g_flags;
    volatile int* vf2 = (volatile int*)g_flags2;
    const int r0s = lane >> 2, c0s = (lane & 3) * 2;

    for (int s = 0; s <= S_; ++s) {
        // prefetch gx0 (flag-independent); clamp at s==S (buffer unread there)
        const int sg = (s < S_) ? s : (S_ - 1);
        float pre[2][4];
#pragma unroll
        for (int ci = 0; ci < 2; ++ci) {
            int j = cta * 8 + jl0 + ci * 4;
            const float* gp = gx + ((size_t)sg * G4_ + j) * B_ + n;
            pre[ci][0] = gp[0];
            pre[ci][1] = gp[(size_t)1 * H_ * B_];
            pre[ci][2] = gp[(size_t)2 * H_ * B_];
            pre[ci][3] = gp[(size_t)3 * H_ * B_];
        }

        float accB[2][8][4];
#pragma unroll
        for (int mt = 0; mt < 2; ++mt)
#pragma unroll
            for (int nt = 0; nt < 8; ++nt)
#pragma unroll
                for (int q = 0; q < 4; ++q) accB[mt][nt][q] = 0.f;

        // ---- phase R: Whh1 @ h2[s-2], gated only by epoch2 (published early) ----
        if (s >= 2) {
            if (cta == 0) {
                if (tid < NCTA) { while (vf2[tid] < s - 1) {} }
                __syncthreads();
                if (tid == 0) vf2[EPOCH] = s - 1;
            } else {
                if (tid == 0) { while (vf2[EPOCH] < s - 1) {} }
                __syncthreads();
            }
            __threadfence();

            const uint4* hb2 = (const uint4*)g_h2frag + (size_t)(s & 1) * 8192;
#pragma unroll
            for (int kt = 0; kt < 8; ++kt) {
                uint4 a0v = wfR[(size_t)kt * 32];
                uint4 a1v = wfR[(size_t)(8 + kt) * 32];
                unsigned Ar0[4] = {a0v.x, a0v.y, a0v.z, a0v.w};
                unsigned Ar1[4] = {a1v.x, a1v.y, a1v.z, a1v.w};
                const uint4* kb = hb2 + ((size_t)(w * 8 + kt) * 4) * 32 + lane;
#pragma unroll
                for (int ntp = 0; ntp < 4; ++ntp) {
                    uint4 Bv = kb[ntp * 32];
                    int nt0 = ntp * 2, nt1 = ntp * 2 + 1;
                    mma16816(accB[0][nt0], Ar0, Bv.x, Bv.y);
                    mma16816(accB[1][nt0], Ar1, Bv.x, Bv.y);
                    mma16816(accB[0][nt1], Ar0, Bv.z, Bv.w);
                    mma16816(accB[1][nt1], Ar1, Bv.z, Bv.w);
                }
            }
        }

        // ---- wait epoch1 (h1[s-1]), then merged GEMM ----
        if (s >= 1) {
            if (cta == 0) {
                if (tid < NCTA) { while (vf1[tid] < s) {} }
                __syncthreads();
                if (tid == 0) vf1[EPOCH] = s;
            } else {
                if (tid == 0) { while (vf1[EPOCH] < s) {} }
                __syncthreads();
            }
            __threadfence();

            float accA[2][8][4];
#pragma unroll
            for (int mt = 0; mt < 2; ++mt)
#pragma unroll
                for (int nt = 0; nt < 8; ++nt)
#pragma unroll
                    for (int q = 0; q < 4; ++q) accA[mt][nt][q] = 0.f;

            const uint4* hb = (const uint4*)g_h1frag + (size_t)((s - 1) & 1) * 8192;
#pragma unroll
            for (int kt = 0; kt < 8; ++kt) {
                uint4 a0v = wfI[(size_t)kt * 32];
                uint4 a1v = wfI[(size_t)(8 + kt) * 32];
                unsigned Ai0[4] = {a0v.x, a0v.y, a0v.z, a0v.w};
                unsigned Ai1[4] = {a1v.x, a1v.y, a1v.z, a1v.w};
                const uint4* kb = hb + ((size_t)(w * 8 + kt) * 4) * 32 + lane;
#pragma unroll
                for (int ntp = 0; ntp < 4; ++ntp) {
                    uint4 Bv = kb[ntp * 32];
                    int nt0 = ntp * 2, nt1 = ntp * 2 + 1;
                    mma16816(accA[0][nt0], A0[0][kt], Bv.x, Bv.y);
                    mma16816(accA[1][nt0], A0[1][kt], Bv.x, Bv.y);
                    mma16816(accA[0][nt1], A0[0][kt], Bv.z, Bv.w);
                    mma16816(accA[1][nt1], A0[1][kt], Bv.z, Bv.w);
                    mma16816(accB[0][nt0], Ai0, Bv.x, Bv.y);
                    mma16816(accB[1][nt0], Ai1, Bv.x, Bv.y);
                    mma16816(accB[0][nt1], Ai0, Bv.z, Bv.w);
                    mma16816(accB[1][nt1], Ai1, Bv.z, Bv.w);
                }
            }

#pragma unroll
            for (int mt = 0; mt < 2; ++mt)
#pragma unroll
                for (int nt = 0; nt < 8; ++nt) {
                    float* dA = RbufA + ((size_t)w * 32 + mt * 16 + r0s) * RSTR + nt * 8 + c0s;
                    *(float2*)dA = make_float2(accA[mt][nt][0], accA[mt][nt][1]);
                    *(float2*)(dA + 8 * RSTR) = make_float2(accA[mt][nt][2], accA[mt][nt][3]);
                    float* dB = RbufB + ((size_t)w * 32 + mt * 16 + r0s) * RSTR + nt * 8 + c0s;
                    *(float2*)dB = make_float2(accB[mt][nt][0], accB[mt][nt][1]);
                    *(float2*)(dB + 8 * RSTR) = make_float2(accB[mt][nt][2], accB[mt][nt][3]);
                }
        }
        __syncthreads();

        // ---- epilogue B: h2[s-1] + early flag2 ----
        float h2v[2];
        if (s >= 1) {
#pragma unroll
            for (int ci = 0; ci < 2; ++ci) {
                int jloc = jl0 + ci * 4;
                int j = cta * 8 + jloc;
                float pi = b1v[ci][0], pf = b1v[ci][1], pg = b1v[ci][2], po = b1v[ci][3];
#pragma unroll
                for (int w8 = 0; w8 < 8; ++w8) {
                    const float* rp = RbufB + ((size_t)w8 * 32 + jloc * 4) * RSTR + n;
                    pi += rp[0];
                    pf += rp[RSTR];
                    pg += rp[2 * RSTR];
                    po += rp[3 * RSTR];
                }
                float iv = sigf(pi), fv = sigf(pf), gv = tanhf_(pg), ov = sigf(po);
                c1[ci] = fv * c1[ci] + iv * gv;
                float h = ov * tanhf_(c1[ci]);
                h2v[ci] = h;

                unsigned short hh = f16of(h);
                int ktile = j >> 4, kk = j & 15;
                int nt = n >> 3;
                int flane = (n & 7) * 4 + ((kk & 7) >> 1);
                size_t byte = (((size_t)(ktile * 4 + (nt >> 1)) * 32 + flane) * 16)
                              + (size_t)(nt & 1) * 8 + (kk >> 3) * 4 + (kk & 1) * 2;
                *(unsigned short*)(g_h2frag + (size_t)((s - 1) & 1) * 131072 + byte) = hh;
            }
            __threadfence();
        }
        __syncthreads();
        if (s >= 1 && tid == 0) vf2[cta] = s;    // h2[s-1] published (early)

        // ---- epilogue A: h1[s] ----
        {
            unsigned char* hfd = g_h1frag + (size_t)(s & 1) * 131072;
#pragma unroll
            for (int ci = 0; ci < 2; ++ci) {
                int jloc = jl0 + ci * 4;
                int j = cta * 8 + jloc;
                float pi = pre[ci][0], pf = pre[ci][1], pg = pre[ci][2], po = pre[ci][3];
                if (s > 0) {
#pragma unroll
                    for (int w8 = 0; w8 < 8; ++w8) {
                        const float* rp = RbufA + ((size_t)w8 * 32 + jloc * 4) * RSTR + n;
                        pi += rp[0];
                        pf += rp[RSTR];
                        pg += rp[2 * RSTR];
                        po += rp[3 * RSTR];
                    }
                }
                float iv = sigf(pi), fv = sigf(pf), gv = tanhf_(pg), ov = sigf(po);
                c0[ci] = fv * c0[ci] + iv * gv;
                float h = ov * tanhf_(c0[ci]);

                unsigned short hh = f16of(h);
                int ktile = j >> 4, kk = j & 15;
                int nt = n >> 3;
                int flane = (n & 7) * 4 + ((kk & 7) >> 1);
                size_t byte = (((size_t)(ktile * 4 + (nt >> 1)) * 32 + flane) * 16)
                              + (size_t)(nt & 1) * 8 + (kk >> 3) * 4 + (kk & 1) * 2;
                *(unsigned short*)(hfd + byte) = hh;
            }
        }

        __threadfence();
        __syncthreads();
        if (tid == 0) vf1[cta] = s + 1;          // h1[s] published

        // fp32 h2 stores: off the inter-CTA critical path
        if (s >= 1) {
#pragma unroll
            for (int ci = 0; ci < 2; ++ci) {
                int j = cta * 8 + jl0 + ci * 4;
                hseq2[((size_t)(s - 1) * H_ + j) * B_ + n] = h2v[ci];
            }
        }
    }
}

// ---------------- fused transpose + sigmoid(relu) ----------------
__global__ void __launch_bounds__(256)
act_out_kernel(const float* __restrict__ h2, float* __restrict__ out)
{
    __shared__ float T[64][68];
    const int s = blockIdx.y, jt = blockIdx.x, t = threadIdx.x;
    {
        int jj0 = (t >> 4) * 4, bq = (t & 15) * 4;
#pragma unroll
        for (int r = 0; r < 4; ++r)
            *(float4*)&T[jj0 + r][bq] =
                *(const float4*)(h2 + ((size_t)s * H_ + jt * 64 + jj0 + r) * B_ + bq);
    }
    __syncthreads();
    {
        int b0 = (t >> 4) * 4, jq = (t & 15) * 4;
#pragma unroll
        for (int i = 0; i < 4; ++i) {
            int b = b0 + i;
            float4 w;
            w.x = actf(T[jq + 0][b]); w.y = actf(T[jq + 1][b]);
            w.z = actf(T[jq + 2][b]); w.w = actf(T[jq + 3][b]);
            *(float4*)(out + (size_t)b * (S_ * H_) + (size_t)s * H_ + jt * 64 + jq) = w;
        }
    }
}

// ---------------- launcher ----------------
extern "C" void kernel_launch(void* const* d_in, const int* in_sizes, int n_in,
                              void* d_out, int out_size)
{
    const float* x    = (const float*)d_in[0];
    const float* Wih0 = (const float*)d_in[1];
    const float* Whh0 = (const float*)d_in[2];
    const float* bih0 = (const float*)d_in[3];
    const float* bhh0 = (const float*)d_in[4];
    const float* Wih1 = (const float*)d_in[5];
    const float* Whh1 = (const float*)d_in[6];
    const float* bih1 = (const float*)d_in[7];
    const float* bhh1 = (const float*)d_in[8];
    float* out = (float*)d_out;

    float *gx, *h2;
    unsigned char* wi;
    unsigned char* xf;
    cudaGetSymbolAddress((void**)&gx, g_gx);
    cudaGetSymbolAddress((void**)&h2, g_h2);
    cudaGetSymbolAddress((void**)&wi, g_WI);
    cudaGetSymbolAddress((void**)&xf, g_xf);

    const int smem_rec  = 2 * 8 * 32 * RSTR * (int)sizeof(float);  // 135168
    const int smem_gemm = 2 * 2048 * (int)sizeof(uint4);           // 65536
    cudaFuncSetAttribute(fused_recur_kernel, cudaFuncAttributeMaxDynamicSharedMemorySize, smem_rec);
    cudaFuncSetAttribute(gemm_mma_kernel<32>, cudaFuncAttributeMaxDynamicSharedMemorySize, smem_gemm);

    // one-shot preps
    prep_w_kernel<<<6144, 256>>>(Whh0, Whh1, Wih1);
    prep_wi_kernel<32, D_><<<1024, 256>>>(Wih0);
    conv_x0_kernel<<<8192, 256>>>(x);

    // layer0 input GEMM
    dim3 ggrid(32, 128);
    gemm_mma_kernel<32><<<ggrid, 256, smem_gemm>>>((const uint4*)wi, (const uint4*)xf, bih0, bhh0, gx);

    // fused two-layer recurrence (dual-epoch pipelined)
    reset_flags_kernel<<<1, 256>>>();
    fused_recur_kernel<<<NCTA, 256, smem_rec>>>(gx, bih1, bhh1, h2);

    // epilogue
    dim3 agrid(H_ / 64, S_);
    act_out_kernel<<<agrid, 256>>>(h2, out);
}

// round 14
// speedup vs baseline: 1.2428x; 1.2428x over previous
#include <cuda_runtime.h>
#include <cuda_bf16.h>
#include <cuda_fp16.h>
#include <cstdint>
#include <cstddef>

#define B_   64
#define S_   256
#define D_   512
#define H_   1024
#define G4_  4096
#define NCTA 128
#define RSTR 66
#define EPOCH 255

// ---------------- scratch (device globals) ----------------
__device__ __align__(128) float g_gx[67108864];            // [S][4H][B] (layer0 only)
__device__ __align__(128) float g_h2[16777216];            // [S][H][B]
__device__ __align__(128) unsigned char g_WF[33554432];    // A fragments: slot0=Whh0, slot1=Whh1, slot2=Wih1
__device__ __align__(128) unsigned char g_WI[8388608];     // layer0 input-GEMM A fragments
__device__ __align__(128) unsigned char g_xf[16777216];    // layer0 input-GEMM B fragments
__device__ __align__(128) unsigned char g_h1frag[262144];  // [buf][...] h1 fragments (fp16)
__device__ __align__(128) unsigned char g_h2frag[262144];  // [buf][...] h2 fragments (fp16)
__device__ int g_flags[256];

// ---------------- helpers ----------------
__device__ __forceinline__ float sigf(float x)   { return 1.f / (1.f + __expf(-x)); }
__device__ __forceinline__ float tanhf_(float x) { return 2.f / (1.f + __expf(-2.f * x)) - 1.f; }
__device__ __forceinline__ float actf(float x)   { return x > 0.f ? 1.f / (1.f + __expf(-x)) : 0.5f; }

__device__ __forceinline__ unsigned short f16of(float v) {
    __half h = __float2half(v);
    return *(unsigned short*)&h;
}
__device__ __forceinline__ int ld_acq(const int* p) {
    int v;
    asm volatile("ld.acquire.gpu.global.b32 %0, [%1];" : "=r"(v) : "l"(p) : "memory");
    return v;
}
__device__ __forceinline__ void st_rel(int* p, int v) {
    asm volatile("st.release.gpu.global.b32 [%0], %1;" :: "l"(p), "r"(v) : "memory");
}

__device__ __forceinline__ void mma16816(float* d, const unsigned* a, unsigned b0, unsigned b1) {
    asm volatile("mma.sync.aligned.m16n8k16.row.col.f32.f16.f16.f32 "
                 "{%0,%1,%2,%3}, {%4,%5,%6,%7}, {%8,%9}, {%0,%1,%2,%3};"
                 : "+f"(d[0]), "+f"(d[1]), "+f"(d[2]), "+f"(d[3])
                 : "r"(a[0]), "r"(a[1]), "r"(a[2]), "r"(a[3]), "r"(b0), "r"(b1));
}

// B-fragment byte offset within one s (validated layout)
__device__ __forceinline__ size_t xf_byte(int k, int n) {
    int ktile = k >> 4, kk = k & 15;
    int nt = n >> 3;
    int flane = (n & 7) * 4 + ((kk & 7) >> 1);
    return (((size_t)(ktile * 4 + (nt >> 1)) * 32 + flane) * 16)
           + (size_t)(nt & 1) * 8 + (kk >> 3) * 4 + (kk & 1) * 2;
}

// ---------------- prep: W_ih0 -> A fragments (fp16) ----------------
template<int KT, int KDIM>
__global__ void __launch_bounds__(256)
prep_wi_kernel(const float* __restrict__ W)
{
    unsigned idx  = blockIdx.x * 256 + threadIdx.x;
    unsigned lane = idx & 31;
    unsigned kt   = (idx >> 5) & (KT - 1);
    unsigned w    = (idx >> 5) / KT & 7;
    unsigned gt   = (idx >> 5) / KT >> 3;

    unsigned hi[4];
#pragma unroll
    for (int p = 0; p < 4; ++p) {
        unsigned r = (lane >> 2) + (p & 1) * 8;
        unsigned c = (lane & 3) * 2 + (p >> 1) * 8;
        unsigned row = gt * 128 + w * 16 + r;
        unsigned k = kt * 16 + c;
        float2 v = *(const float2*)(W + (size_t)row * KDIM + k);
        hi[p] = (unsigned)f16of(v.x) | ((unsigned)f16of(v.y) << 16);
    }
    size_t fu = ((size_t)(gt * 8 + w) * KT + kt) * 32 + lane;
    ((uint4*)g_WI)[fu] = make_uint4(hi[0], hi[1], hi[2], hi[3]);
}

// ---------------- conv: x [B][S][D] -> B fragments (K=512) ----------------
__global__ void __launch_bounds__(256)
conv_x0_kernel(const float* __restrict__ x)
{
    unsigned idx = blockIdx.x * 256 + threadIdx.x;
    unsigned k4  = idx & 127;
    unsigned n   = (idx >> 7) & 63;
    unsigned s   = idx >> 13;
    float4 v = *(const float4*)(x + ((size_t)n * S_ + s) * D_ + k4 * 4);
    unsigned char* bs = g_xf + (size_t)s * 65536;
    int k = k4 * 4;
    unsigned u0 = (unsigned)f16of(v.x) | ((unsigned)f16of(v.y) << 16);
    unsigned u1 = (unsigned)f16of(v.z) | ((unsigned)f16of(v.w) << 16);
    *(unsigned*)(bs + xf_byte(k, n))     = u0;
    *(unsigned*)(bs + xf_byte(k + 2, n)) = u1;
}

// ---------------- tensor-core layer0 input GEMM with smem B staging ----------------
template<int KT>
__global__ void __launch_bounds__(256)
gemm_mma_kernel(const uint4* __restrict__ WI, const uint4* __restrict__ XF,
                const float* __restrict__ bA, const float* __restrict__ bB,
                float* __restrict__ gx)
{
    extern __shared__ uint4 Bs[];   // [2][2048]
    const int tid = threadIdx.x, w = tid >> 5, lane = tid & 31;
    const int gt = blockIdx.x;
    const int s0 = blockIdx.y * 2;
    const int NCHUNK = KT / 8;

    float acc[2][8][4];
#pragma unroll
    for (int si = 0; si < 2; ++si)
#pragma unroll
        for (int nt = 0; nt < 8; ++nt)
#pragma unroll
            for (int q = 0; q < 4; ++q) acc[si][nt][q] = 0.f;

    const uint4* ap = WI + ((size_t)(gt * 8 + w) * KT) * 32 + lane;

    auto issue_chunk = [&](int c, int buf) {
        const uint4* base0 = XF + (size_t)s0 * (KT * 128) + c * 1024;
        const uint4* base1 = base0 + KT * 128;
#pragma unroll
        for (int i = 0; i < 8; ++i) {
            int e = tid + i * 256;
            const uint4* src = (e < 1024) ? (base0 + e) : (base1 + (e - 1024));
            unsigned dst = (unsigned)__cvta_generic_to_shared(Bs + buf * 2048 + e);
            asm volatile("cp.async.cg.shared.global [%0], [%1], 16;" :: "r"(dst), "l"(src));
        }
        asm volatile("cp.async.commit_group;" ::: "memory");
    };

    issue_chunk(0, 0);
    asm volatile("cp.async.wait_group 0;" ::: "memory");
    __syncthreads();

    int buf = 0;
    for (int c = 0; c < NCHUNK; ++c) {
        if (c < NCHUNK - 1) issue_chunk(c + 1, buf ^ 1);

        uint4 As[8];
#pragma unroll
        for (int ktl = 0; ktl < 8; ++ktl) As[ktl] = ap[(size_t)(c * 8 + ktl) * 32];
#pragma unroll
        for (int ktl = 0; ktl < 8; ++ktl) {
            unsigned Ah[4] = {As[ktl].x, As[ktl].y, As[ktl].z, As[ktl].w};
            const uint4* q0 = Bs + buf * 2048 + ktl * 128 + lane;
            const uint4* q1 = q0 + 1024;
#pragma unroll
            for (int ntp = 0; ntp < 4; ++ntp) {
                uint4 B0 = q0[ntp * 32];
                mma16816(acc[0][ntp * 2],     Ah, B0.x, B0.y);
                mma16816(acc[0][ntp * 2 + 1], Ah, B0.z, B0.w);
                uint4 B1 = q1[ntp * 32];
                mma16816(acc[1][ntp * 2],     Ah, B1.x, B1.y);
                mma16816(acc[1][ntp * 2 + 1], Ah, B1.z, B1.w);
            }
        }
        if (c < NCHUNK - 1) {
            asm volatile("cp.async.wait_group 0;" ::: "memory");
            __syncthreads();
            buf ^= 1;
        }
    }

    const int r0 = lane >> 2, c0 = (lane & 3) * 2;
    const int gl = gt * 128 + w * 16 + r0;
    const float biasL = bA[gl] + bB[gl];
    const float biasH = bA[gl + 8] + bB[gl + 8];
#pragma unroll
    for (int si = 0; si < 2; ++si) {
        float* gxs = gx + (size_t)(s0 + si) * G4_ * B_;
#pragma unroll
        for (int nt = 0; nt < 8; ++nt) {
            int c = nt * 8 + c0;
            *(float2*)(gxs + (size_t)gl * B_ + c) =
                make_float2(acc[si][nt][0] + biasL, acc[si][nt][1] + biasL);
            *(float2*)(gxs + (size_t)(gl + 8) * B_ + c) =
                make_float2(acc[si][nt][2] + biasH, acc[si][nt][3] + biasH);
        }
    }
}

// ---------------- weight prep: {Whh0, Whh1, Wih1} -> gate-interleaved A fragments ----------------
__global__ void __launch_bounds__(256)
prep_w_kernel(const float* __restrict__ Whh0, const float* __restrict__ Whh1,
              const float* __restrict__ Wih1)
{
    unsigned idx  = blockIdx.x * 256 + threadIdx.x;
    unsigned lane = idx & 31;
    unsigned kt   = (idx >> 5) & 7;
    unsigned mt   = (idx >> 8) & 1;
    unsigned w    = (idx >> 9) & 7;
    unsigned cta  = (idx >> 12) & 127;
    unsigned l    = idx >> 19;
    const float* W = (l == 0) ? Whh0 : (l == 1 ? Whh1 : Wih1);

    unsigned hi[4];
#pragma unroll
    for (int p = 0; p < 4; ++p) {
        unsigned r = (lane >> 2) + (p & 1) * 8;
        unsigned c = (lane & 3) * 2 + (p >> 1) * 8;
        unsigned rloc = mt * 16 + r;
        unsigned gr = cta * 32 + rloc;
        unsigned j = gr >> 2, gate = gr & 3;
        unsigned k = w * 128 + kt * 16 + c;
        float2 v = *(const float2*)(W + ((size_t)(gate * H_ + j)) * H_ + k);
        hi[p] = (unsigned)f16of(v.x) | ((unsigned)f16of(v.y) << 16);
    }
    size_t fr = ((((size_t)(l * 128 + cta) * 8 + w) * 2 + mt) * 8 + kt) * 32 + lane;
    ((uint4*)g_WF)[fr] = make_uint4(hi[0], hi[1], hi[2], hi[3]);
}

__global__ void reset_flags_kernel() { g_flags[threadIdx.x] = 0; }

// ---------------- fused 2-layer wavefront recurrence: 257 supersteps ----------------
// R12 structure; sync via release/acquire flags (no explicit membar on the chain).
__global__ void __launch_bounds__(256, 1)
fused_recur_kernel(const float* __restrict__ gx,
                   const float* __restrict__ bih1, const float* __restrict__ bhh1,
                   float* __restrict__ hseq2)
{
    extern __shared__ float Rbuf[];

    const int tid  = threadIdx.x;
    const int w    = tid >> 5;
    const int lane = tid & 31;
    const int cta  = blockIdx.x;

    // resident A: layer0 recurrence (slot 0)
    unsigned A0[2][8][4];
    {
        const uint4* wf = (const uint4*)g_WF + (((size_t)cta * 8 + w) * 16) * 32 + lane;
#pragma unroll
        for (int mt = 0; mt < 2; ++mt)
#pragma unroll
            for (int kt = 0; kt < 8; ++kt) {
                uint4 h = wf[(size_t)(mt * 8 + kt) * 32];
                A0[mt][kt][0] = h.x; A0[mt][kt][1] = h.y; A0[mt][kt][2] = h.z; A0[mt][kt][3] = h.w;
            }
    }
    const uint4* wfR = (const uint4*)g_WF + (((size_t)(128 + cta) * 8 + w) * 16) * 32 + lane;
    const uint4* wfI = (const uint4*)g_WF + (((size_t)(256 + cta) * 8 + w) * 16) * 32 + lane;

    const int n   = tid & 63;
    const int jl0 = tid >> 6;
    float c0[2] = {0.f, 0.f}, c1[2] = {0.f, 0.f};

    float b1v[2][4];
#pragma unroll
    for (int ci = 0; ci < 2; ++ci) {
        int j = cta * 8 + jl0 + ci * 4;
#pragma unroll
        for (int g = 0; g < 4; ++g) b1v[ci][g] = bih1[g * H_ + j] + bhh1[g * H_ + j];
    }

    const int r0s = lane >> 2, c0s = (lane & 3) * 2;

    for (int s = 0; s <= S_; ++s) {
        // prefetch gx0 (flag-independent); clamp at s==S (buffer unread there)
        const int sg = (s < S_) ? s : (S_ - 1);
        float pre[2][4];
#pragma unroll
        for (int ci = 0; ci < 2; ++ci) {
            int j = cta * 8 + jl0 + ci * 4;
            const float* gp = gx + ((size_t)sg * G4_ + j) * B_ + n;
            pre[ci][0] = gp[0];
            pre[ci][1] = gp[(size_t)1 * H_ * B_];
            pre[ci][2] = gp[(size_t)2 * H_ * B_];
            pre[ci][3] = gp[(size_t)3 * H_ * B_];
        }

        if (s > 0) {
            if (cta == 0) {
                if (tid < NCTA) { while (ld_acq(&g_flags[tid]) < s) {} }
                __syncthreads();
                if (tid == 0) st_rel(&g_flags[EPOCH], s);
            } else {
                if (tid == 0) { while (ld_acq(&g_flags[EPOCH]) < s) {} }
                __syncthreads();
            }
        }

        // ---------------- merged loop: phase A mma + phase B input mma, shared Bv ----------------
        float accBi[2][8][4];
        if (s >= 1) {
            float accA[2][8][4];
#pragma unroll
            for (int mt = 0; mt < 2; ++mt)
#pragma unroll
                for (int nt = 0; nt < 8; ++nt)
#pragma unroll
                    for (int q = 0; q < 4; ++q) { accA[mt][nt][q] = 0.f; accBi[mt][nt][q] = 0.f; }

            const uint4* hb = (const uint4*)g_h1frag + (size_t)((s - 1) & 1) * 8192;
#pragma unroll
            for (int kt = 0; kt < 8; ++kt) {
                uint4 a0v = wfI[(size_t)kt * 32];
                uint4 a1v = wfI[(size_t)(8 + kt) * 32];
                unsigned Ai0[4] = {a0v.x, a0v.y, a0v.z, a0v.w};
                unsigned Ai1[4] = {a1v.x, a1v.y, a1v.z, a1v.w};
                const uint4* kb = hb + ((size_t)(w * 8 + kt) * 4) * 32 + lane;
#pragma unroll
                for (int ntp = 0; ntp < 4; ++ntp) {
                    uint4 Bv = kb[ntp * 32];
                    int nt0 = ntp * 2, nt1 = ntp * 2 + 1;
                    mma16816(accA[0][nt0],  A0[0][kt], Bv.x, Bv.y);
                    mma16816(accA[1][nt0],  A0[1][kt], Bv.x, Bv.y);
                    mma16816(accA[0][nt1],  A0[0][kt], Bv.z, Bv.w);
                    mma16816(accA[1][nt1],  A0[1][kt], Bv.z, Bv.w);
                    mma16816(accBi[0][nt0], Ai0, Bv.x, Bv.y);
                    mma16816(accBi[1][nt0], Ai1, Bv.x, Bv.y);
                    mma16816(accBi[0][nt1], Ai0, Bv.z, Bv.w);
                    mma16816(accBi[1][nt1], Ai1, Bv.z, Bv.w);
                }
            }
#pragma unroll
            for (int mt = 0; mt < 2; ++mt)
#pragma unroll
                for (int nt = 0; nt < 8; ++nt) {
                    float* dst = Rbuf + ((size_t)w * 32 + mt * 16 + r0s) * RSTR + nt * 8 + c0s;
                    *(float2*)dst = make_float2(accA[mt][nt][0], accA[mt][nt][1]);
                    *(float2*)(dst + 8 * RSTR) = make_float2(accA[mt][nt][2], accA[mt][nt][3]);
                }
        }
        __syncthreads();

        // ---------------- epilogue A: h1[s] (garbage at s==S, buffer unread) ----------------
        {
            unsigned char* hfd = g_h1frag + (size_t)(s & 1) * 131072;
#pragma unroll
            for (int ci = 0; ci < 2; ++ci) {
                int jloc = jl0 + ci * 4;
                int j = cta * 8 + jloc;
                float pi = pre[ci][0], pf = pre[ci][1], pg = pre[ci][2], po = pre[ci][3];
                if (s > 0) {
#pragma unroll
                    for (int w8 = 0; w8 < 8; ++w8) {
                        const float* rp = Rbuf + ((size_t)w8 * 32 + jloc * 4) * RSTR + n;
                        pi += rp[0];
                        pf += rp[RSTR];
                        pg += rp[2 * RSTR];
                        po += rp[3 * RSTR];
                    }
                }
                float iv = sigf(pi), fv = sigf(pf), gv = tanhf_(pg), ov = sigf(po);
                c0[ci] = fv * c0[ci] + iv * gv;
                float h = ov * tanhf_(c0[ci]);

                unsigned short hh = f16of(h);
                int ktile = j >> 4, kk = j & 15;
                int nt = n >> 3;
                int flane = (n & 7) * 4 + ((kk & 7) >> 1);
                size_t byte = (((size_t)(ktile * 4 + (nt >> 1)) * 32 + flane) * 16)
                              + (size_t)(nt & 1) * 8 + (kk >> 3) * 4 + (kk & 1) * 2;
                *(unsigned short*)(hfd + byte) = hh;
            }
        }
        __syncthreads();   // Rbuf reuse

        // ---------------- phase B: layer1 recurrence + epilogue, h2[s-1] ----------------
        float h2v[2];
        if (s >= 1) {
            if (s >= 2) {
                const uint4* hb2 = (const uint4*)g_h2frag + (size_t)(s & 1) * 8192;
#pragma unroll
                for (int kt = 0; kt < 8; ++kt) {
                    uint4 a0v = wfR[(size_t)kt * 32];
                    uint4 a1v = wfR[(size_t)(8 + kt) * 32];
                    unsigned Ar0[4] = {a0v.x, a0v.y, a0v.z, a0v.w};
                    unsigned Ar1[4] = {a1v.x, a1v.y, a1v.z, a1v.w};
                    const uint4* kb = hb2 + ((size_t)(w * 8 + kt) * 4) * 32 + lane;
#pragma unroll
                    for (int ntp = 0; ntp < 4; ++ntp) {
                        uint4 Bv = kb[ntp * 32];
                        int nt0 = ntp * 2, nt1 = ntp * 2 + 1;
                        mma16816(accBi[0][nt0], Ar0, Bv.x, Bv.y);
                        mma16816(accBi[1][nt0], Ar1, Bv.x, Bv.y);
                        mma16816(accBi[0][nt1], Ar0, Bv.z, Bv.w);
                        mma16816(accBi[1][nt1], Ar1, Bv.z, Bv.w);
                    }
                }
            }

#pragma unroll
            for (int mt = 0; mt < 2; ++mt)
#pragma unroll
                for (int nt = 0; nt < 8; ++nt) {
                    float* dst = Rbuf + ((size_t)w * 32 + mt * 16 + r0s) * RSTR + nt * 8 + c0s;
                    *(float2*)dst = make_float2(accBi[mt][nt][0], accBi[mt][nt][1]);
                    *(float2*)(dst + 8 * RSTR) = make_float2(accBi[mt][nt][2], accBi[mt][nt][3]);
                }
            __syncthreads();

            unsigned char* hfd2 = g_h2frag + (size_t)((s - 1) & 1) * 131072;
#pragma unroll
            for (int ci = 0; ci < 2; ++ci) {
                int jloc = jl0 + ci * 4;
                int j = cta * 8 + jloc;
                float pi = b1v[ci][0], pf = b1v[ci][1], pg = b1v[ci][2], po = b1v[ci][3];
#pragma unroll
                for (int w8 = 0; w8 < 8; ++w8) {
                    const float* rp = Rbuf + ((size_t)w8 * 32 + jloc * 4) * RSTR + n;
                    pi += rp[0];
                    pf += rp[RSTR];
                    pg += rp[2 * RSTR];
                    po += rp[3 * RSTR];
                }
                float iv = sigf(pi), fv = sigf(pf), gv = tanhf_(pg), ov = sigf(po);
                c1[ci] = fv * c1[ci] + iv * gv;
                float h = ov * tanhf_(c1[ci]);
                h2v[ci] = h;

                unsigned short hh = f16of(h);
                int ktile = j >> 4, kk = j & 15;
                int nt = n >> 3;
                int flane = (n & 7) * 4 + ((kk & 7) >> 1);
                size_t byte = (((size_t)(ktile * 4 + (nt >> 1)) * 32 + flane) * 16)
                              + (size_t)(nt & 1) * 8 + (kk >> 3) * 4 + (kk & 1) * 2;
                *(unsigned short*)(hfd2 + byte) = hh;
            }
        }

        __syncthreads();
        if (tid == 0) st_rel(&g_flags[cta], s + 1);

        if (s >= 1) {
#pragma unroll
            for (int ci = 0; ci < 2; ++ci) {
                int j = cta * 8 + jl0 + ci * 4;
                hseq2[((size_t)(s - 1) * H_ + j) * B_ + n] = h2v[ci];
            }
        }
    }
}

// ---------------- fused transpose + sigmoid(relu) ----------------
__global__ void __launch_bounds__(256)
act_out_kernel(const float* __restrict__ h2, float* __restrict__ out)
{
    __shared__ float T[64][68];
    const int s = blockIdx.y, jt = blockIdx.x, t = threadIdx.x;
    {
        int jj0 = (t >> 4) * 4, bq = (t & 15) * 4;
#pragma unroll
        for (int r = 0; r < 4; ++r)
            *(float4*)&T[jj0 + r][bq] =
                *(const float4*)(h2 + ((size_t)s * H_ + jt * 64 + jj0 + r) * B_ + bq);
    }
    __syncthreads();
    {
        int b0 = (t >> 4) * 4, jq = (t & 15) * 4;
#pragma unroll
        for (int i = 0; i < 4; ++i) {
            int b = b0 + i;
            float4 w;
            w.x = actf(T[jq + 0][b]); w.y = actf(T[jq + 1][b]);
            w.z = actf(T[jq + 2][b]); w.w = actf(T[jq + 3][b]);
            *(float4*)(out + (size_t)b * (S_ * H_) + (size_t)s * H_ + jt * 64 + jq) = w;
        }
    }
}

// ---------------- launcher ----------------
extern "C" void kernel_launch(void* const* d_in, const int* in_sizes, int n_in,
                              void* d_out, int out_size)
{
    const float* x    = (const float*)d_in[0];
    const float* Wih0 = (const float*)d_in[1];
    const float* Whh0 = (const float*)d_in[2];
    const float* bih0 = (const float*)d_in[3];
    const float* bhh0 = (const float*)d_in[4];
    const float* Wih1 = (const float*)d_in[5];
    const float* Whh1 = (const float*)d_in[6];
    const float* bih1 = (const float*)d_in[7];
    const float* bhh1 = (const float*)d_in[8];
    float* out = (float*)d_out;

    float *gx, *h2;
    unsigned char* wi;
    unsigned char* xf;
    cudaGetSymbolAddress((void**)&gx, g_gx);
    cudaGetSymbolAddress((void**)&h2, g_h2);
    cudaGetSymbolAddress((void**)&wi, g_WI);
    cudaGetSymbolAddress((void**)&xf, g_xf);

    const int smem_rec  = 8 * 32 * RSTR * (int)sizeof(float);   // 67584
    const int smem_gemm = 2 * 2048 * (int)sizeof(uint4);        // 65536
    cudaFuncSetAttribute(fused_recur_kernel, cudaFuncAttributeMaxDynamicSharedMemorySize, smem_rec);
    cudaFuncSetAttribute(gemm_mma_kernel<32>, cudaFuncAttributeMaxDynamicSharedMemorySize, smem_gemm);

    // one-shot preps
    prep_w_kernel<<<6144, 256>>>(Whh0, Whh1, Wih1);
    prep_wi_kernel<32, D_><<<1024, 256>>>(Wih0);
    conv_x0_kernel<<<8192, 256>>>(x);

    // layer0 input GEMM
    dim3 ggrid(32, 128);
    gemm_mma_kernel<32><<<ggrid, 256, smem_gemm>>>((const uint4*)wi, (const uint4*)xf, bih0, bhh0, gx);

    // fused two-layer recurrence
    reset_flags_kernel<<<1, 256>>>();
    fused_recur_kernel<<<NCTA, 256, smem_rec>>>(gx, bih1, bhh1, h2);

    // epilogue
    dim3 agrid(H_ / 64, S_);
    act_out_kernel<<<agrid, 256>>>(h2, out);
}